// round 5
// baseline (speedup 1.0000x reference)
#include <cuda_runtime.h>
#include <cstddef>

#define N_NODES 1500
#define D_VC    8
#define E_DIM   64
#define N_EDGES 24000
#define N_LOOP  10
#define WPB     8     // warps per block
#define EB      4     // edges per warp

// ---------------- device scratch (static, allocation-free) ----------------
__device__ __align__(16) float    g_vc [N_NODES * D_VC];
__device__ __align__(16) float    g_goal[D_VC];
__device__ __align__(16) float    g_x  [N_NODES * E_DIM];
__device__ __align__(16) float    g_y  [N_EDGES * E_DIM];
__device__ __align__(16) float    g_PA [N_NODES * E_DIM];   // x @ A_fx  (indexed by src in fx)
__device__ __align__(16) float    g_PB [N_NODES * E_DIM];   // x @ B_fx  (indexed by tgt in fx)
__device__ __align__(16) float    g_RA [N_NODES * E_DIM];   // x @ A_fy  (indexed by tgt in fy)
__device__ __align__(16) float    g_RB [N_NODES * E_DIM];   // x @ B_fy  (indexed by src in fy)
__device__ __align__(16) float    g_Pv [N_NODES * E_DIM];   // vc @ A_hy (indexed by tgt)
__device__ __align__(16) float    g_Qv [N_NODES * E_DIM];   // vc @ B_hy (indexed by src)
__device__ __align__(16) unsigned g_agg[N_NODES * E_DIM];
__device__ __align__(16) float    g_Afx[E_DIM * E_DIM];
__device__ __align__(16) float    g_Bfx[E_DIM * E_DIM];
__device__ __align__(16) float    g_Cfx[E_DIM * E_DIM];
__device__ __align__(16) float    g_Afy[E_DIM * E_DIM];
__device__ __align__(16) float    g_Bfy[E_DIM * E_DIM];
__device__ __align__(16) float    g_Ahy[D_VC * E_DIM];
__device__ __align__(16) float    g_Bhy[D_VC * E_DIM];
__device__ int g_winner[N_NODES * N_NODES];

// ---------------- order-preserving float<->u32 encoding for atomicMax ------
// finite floats always encode to values > 0, so 0 is the "empty segment" sentinel.
__device__ __forceinline__ unsigned encf(float f) {
    unsigned u = __float_as_uint(f);
    return (u & 0x80000000u) ? ~u : (u | 0x80000000u);
}
__device__ __forceinline__ float decf(unsigned e) {
    return __uint_as_float((e & 0x80000000u) ? (e & 0x7FFFFFFFu) : ~e);
}

// ---------------- prep kernels --------------------------------------------
__global__ void k_prep0(const float* __restrict__ v, const float* __restrict__ labels) {
    int n = blockIdx.x * blockDim.x + threadIdx.x;
    if (n >= N_NODES) return;
    float row[D_VC];
#pragma unroll
    for (int c = 0; c < 7; c++) row[c] = v[n * 7 + c];
    row[7] = labels[n];
#pragma unroll
    for (int c = 0; c < 8; c++) g_vc[n * 8 + c] = row[c];
    if (row[7] > 0.5f) {
#pragma unroll
        for (int c = 0; c < 8; c++) g_goal[c] = row[c];
    }
}

// Fold layer-1 weights of the concat MLPs:
//  fx: in = [xj-xi, xj, xi, y], xi=x[tgt], xj=x[src]
//      -> x[src]@(W1a+W1b) + x[tgt]@(W1c-W1a) + y@W1d
//  fy: in = [xj2-xi2, xj2, xi2], xi2=x[src], xj2=x[tgt]
//      -> x[tgt]@(W1a+W1b) + x[src]@(W1c-W1a)
//  hy: in = [vj-vi, vj, vi], vi=vc[src], vj=vc[tgt]
//      -> vc[tgt]@(W1a+W1b) + vc[src]@(W1c-W1a)
__global__ void k_combine(const float* __restrict__ fxW1,
                          const float* __restrict__ fyW1,
                          const float* __restrict__ hyW1) {
    int i = blockIdx.x * blockDim.x + threadIdx.x;
    if (i < 4096) {
        float a = fxW1[i];
        g_Afx[i] = a + fxW1[4096 + i];
        g_Bfx[i] = fxW1[8192 + i] - a;
        g_Cfx[i] = fxW1[12288 + i];
        float b = fyW1[i];
        g_Afy[i] = b + fyW1[4096 + i];
        g_Bfy[i] = fyW1[8192 + i] - b;
    }
    if (i < 512) {
        float c = hyW1[i];
        g_Ahy[i] = c + hyW1[512 + i];
        g_Bhy[i] = hyW1[1024 + i] - c;
    }
}

__global__ void k_prep_pv() {
    int i = blockIdx.x * blockDim.x + threadIdx.x;
    if (i >= N_NODES * E_DIM) return;
    int n = i >> 6, j = i & 63;
    float s = 0.f, q = 0.f;
#pragma unroll
    for (int k = 0; k < 8; k++) {
        float vk = g_vc[n * 8 + k];
        s += vk * g_Ahy[k * 64 + j];
        q += vk * g_Bhy[k * 64 + j];
    }
    g_Pv[i] = s;
    g_Qv[i] = q;
}

// ---------------- hx: x init MLP (per node) -------------------------------
__global__ void k_hx(const float* __restrict__ W1, const float* __restrict__ b1,
                     const float* __restrict__ W2, const float* __restrict__ b2) {
    __shared__ __align__(16) float sW1[32 * 64];
    __shared__ __align__(16) float sW2[64 * 64];
    __shared__ float sB1[64], sB2[64];
    __shared__ __align__(16) float sIn[WPB][32];
    __shared__ __align__(16) float sH[WPB][64];
    int tid = threadIdx.x;
    for (int i = tid; i < 2048; i += 256) sW1[i] = W1[i];
    for (int i = tid; i < 4096; i += 256) sW2[i] = W2[i];
    if (tid < 64) { sB1[tid] = b1[tid]; sB2[tid] = b2[tid]; }
    __syncthreads();
    int w = tid >> 5, l = tid & 31;
    int n = blockIdx.x * WPB + w;
    if (n >= N_NODES) return;
    {
        int g = l >> 3, r = l & 7;
        float vcv = g_vc[n * 8 + r];
        float gv  = g_goal[r];
        float dd  = vcv - gv;
        float val = (g == 0) ? vcv : (g == 1) ? gv : (g == 2) ? dd : dd * dd;
        sIn[w][l] = val;
    }
    __syncwarp();
    const float2* sW1_2 = (const float2*)sW1;
    float2 acc = ((const float2*)sB1)[l];
#pragma unroll 8
    for (int k = 0; k < 32; k++) {
        float vk  = sIn[w][k];
        float2 wv = sW1_2[k * 32 + l];
        acc.x += vk * wv.x; acc.y += vk * wv.y;
    }
    acc.x = fmaxf(acc.x, 0.f); acc.y = fmaxf(acc.y, 0.f);
    ((float2*)sH[w])[l] = acc;
    __syncwarp();
    const float2* sW2_2 = (const float2*)sW2;
    float2 o = ((const float2*)sB2)[l];
#pragma unroll 8
    for (int k = 0; k < 64; k++) {
        float hk  = sH[w][k];
        float2 wv = sW2_2[k * 32 + l];
        o.x += hk * wv.x; o.y += hk * wv.y;
    }
    ((float2*)g_x)[n * 32 + l] = o;
}

// ---------------- x update (+agg reset) + all 4 node projections ----------
__global__ void k_xupdate(int initmode) {
    __shared__ __align__(16) float xs[WPB][64];
    int tid = threadIdx.x, w = tid >> 5, l = tid & 31;
    int n = blockIdx.x * WPB + w;
    if (n >= N_NODES) return;
    float2* x2 = (float2*)g_x;
    float2 xv = x2[n * 32 + l];
    if (!initmode) {
        int base = n * 64 + 2 * l;
        unsigned a0 = g_agg[base], a1 = g_agg[base + 1];
        g_agg[base] = 0u; g_agg[base + 1] = 0u;
        float f0 = a0 ? decf(a0) : 0.f;   // empty segment -> 0 (PyG semantics)
        float f1 = a1 ? decf(a1) : 0.f;
        xv.x = fmaxf(xv.x, f0); xv.y = fmaxf(xv.y, f1);
        x2[n * 32 + l] = xv;
    }
    ((float2*)xs[w])[l] = xv;
    __syncwarp();
    const float2* WA = (const float2*)g_Afx;
    const float2* WB = (const float2*)g_Bfx;
    const float2* WC = (const float2*)g_Afy;
    const float2* WD = (const float2*)g_Bfy;
    float2 aA = make_float2(0.f, 0.f), aB = aA, aC = aA, aD = aA;
#pragma unroll 4
    for (int k = 0; k < 64; k++) {
        float xk = xs[w][k];
        float2 wa = __ldg(WA + k * 32 + l);
        float2 wb = __ldg(WB + k * 32 + l);
        float2 wc = __ldg(WC + k * 32 + l);
        float2 wd = __ldg(WD + k * 32 + l);
        aA.x += xk * wa.x; aA.y += xk * wa.y;
        aB.x += xk * wb.x; aB.y += xk * wb.y;
        aC.x += xk * wc.x; aC.y += xk * wc.y;
        aD.x += xk * wd.x; aD.y += xk * wd.y;
    }
    ((float2*)g_PA)[n * 32 + l] = aA;
    ((float2*)g_PB)[n * 32 + l] = aB;
    ((float2*)g_RA)[n * 32 + l] = aC;
    ((float2*)g_RB)[n * 32 + l] = aD;
}

// ---------------- fx message kernel: msg = mlp(...), atomicMax scatter ----
__global__ void k_edge_fx(const int* __restrict__ ei,
                          const float* __restrict__ b1,
                          const float* __restrict__ W2,
                          const float* __restrict__ b2) {
    __shared__ __align__(16) float sW1[64 * 64];   // C_fx (y weights)
    __shared__ __align__(16) float sW2[64 * 64];
    __shared__ __align__(16) float sStage[WPB][EB][64];
    __shared__ float sB1[64], sB2[64];
    int tid = threadIdx.x;
    for (int i = tid; i < 4096; i += 256) { sW1[i] = g_Cfx[i]; sW2[i] = W2[i]; }
    if (tid < 64) { sB1[tid] = b1[tid]; sB2[tid] = b2[tid]; }
    __syncthreads();
    int w = tid >> 5, l = tid & 31;
    int ebase = (blockIdx.x * WPB + w) * EB;
    const float2* PA2 = (const float2*)g_PA;
    const float2* PB2 = (const float2*)g_PB;
    const float2* y2  = (const float2*)g_y;
    float2 b1v = ((const float2*)sB1)[l];
    int src[EB], tgt[EB];
    float2 acc[EB];
#pragma unroll
    for (int e = 0; e < EB; e++) {
        int eg = ebase + e;
        bool valid = (eg < N_EDGES);
        int eg0 = valid ? eg : 0;
        src[e] = ei[eg0];
        tgt[e] = ei[N_EDGES + eg0];
        float2 pa = PA2[src[e] * 32 + l];
        float2 pb = PB2[tgt[e] * 32 + l];
        acc[e].x = pa.x + pb.x + b1v.x;
        acc[e].y = pa.y + pb.y + b1v.y;
        ((float2*)sStage[w][e])[l] = y2[(size_t)eg0 * 32 + l];
    }
    __syncwarp();
    const float2* sW1_2 = (const float2*)sW1;
#pragma unroll 8
    for (int k = 0; k < 64; k++) {
        float2 wv = sW1_2[k * 32 + l];
#pragma unroll
        for (int e = 0; e < EB; e++) {
            float yk = sStage[w][e][k];
            acc[e].x += yk * wv.x; acc[e].y += yk * wv.y;
        }
    }
    __syncwarp();
#pragma unroll
    for (int e = 0; e < EB; e++) {
        float2 h;
        h.x = fmaxf(acc[e].x, 0.f); h.y = fmaxf(acc[e].y, 0.f);
        ((float2*)sStage[w][e])[l] = h;
    }
    __syncwarp();
    const float2* sW2_2 = (const float2*)sW2;
    float2 b2v = ((const float2*)sB2)[l];
    float2 out[EB];
#pragma unroll
    for (int e = 0; e < EB; e++) out[e] = b2v;
#pragma unroll 8
    for (int k = 0; k < 64; k++) {
        float2 wv = sW2_2[k * 32 + l];
#pragma unroll
        for (int e = 0; e < EB; e++) {
            float hk = sStage[w][e][k];
            out[e].x += hk * wv.x; out[e].y += hk * wv.y;
        }
    }
#pragma unroll
    for (int e = 0; e < EB; e++) {
        int eg = ebase + e;
        if (eg >= N_EDGES) break;
        unsigned* ap = g_agg + tgt[e] * 64 + 2 * l;
        atomicMax(ap,     encf(out[e].x));
        atomicMax(ap + 1, encf(out[e].y));
    }
}

// ---------------- generic per-edge 2-layer MLP (hy init / fy update) ------
// which==0: hy init  (projT=g_Pv, projS=g_Qv, y = result)
// which==1: fy       (projT=g_RA, projS=g_RB, y = max(y, result))
__global__ void k_edge_simple(const int* __restrict__ ei,
                              const float* __restrict__ b1,
                              const float* __restrict__ W2,
                              const float* __restrict__ b2,
                              int which) {
    __shared__ __align__(16) float sW2[64 * 64];
    __shared__ __align__(16) float sStage[WPB][EB][64];
    __shared__ float sB1[64], sB2[64];
    int tid = threadIdx.x;
    for (int i = tid; i < 4096; i += 256) sW2[i] = W2[i];
    if (tid < 64) { sB1[tid] = b1[tid]; sB2[tid] = b2[tid]; }
    __syncthreads();
    int w = tid >> 5, l = tid & 31;
    int ebase = (blockIdx.x * WPB + w) * EB;
    const float2* PT2 = (const float2*)(which ? g_RA : g_Pv);
    const float2* PS2 = (const float2*)(which ? g_RB : g_Qv);
    float2 b1v = ((const float2*)sB1)[l];
    int eg0[EB];
    bool valid[EB];
#pragma unroll
    for (int e = 0; e < EB; e++) {
        int eg = ebase + e;
        valid[e] = (eg < N_EDGES);
        eg0[e] = valid[e] ? eg : 0;
        int s = ei[eg0[e]];
        int t = ei[N_EDGES + eg0[e]];
        float2 pt = PT2[t * 32 + l];
        float2 ps = PS2[s * 32 + l];
        float2 h;
        h.x = fmaxf(pt.x + ps.x + b1v.x, 0.f);
        h.y = fmaxf(pt.y + ps.y + b1v.y, 0.f);
        ((float2*)sStage[w][e])[l] = h;
    }
    __syncwarp();
    const float2* sW2_2 = (const float2*)sW2;
    float2 b2v = ((const float2*)sB2)[l];
    float2 out[EB];
#pragma unroll
    for (int e = 0; e < EB; e++) out[e] = b2v;
#pragma unroll 8
    for (int k = 0; k < 64; k++) {
        float2 wv = sW2_2[k * 32 + l];
#pragma unroll
        for (int e = 0; e < EB; e++) {
            float hk = sStage[w][e][k];
            out[e].x += hk * wv.x; out[e].y += hk * wv.y;
        }
    }
    float2* yout = (float2*)g_y;
#pragma unroll
    for (int e = 0; e < EB; e++) {
        if (!valid[e]) break;
        size_t idx = (size_t)eg0[e] * 32 + l;
        if (which) {
            float2 old = yout[idx];
            out[e].x = fmaxf(out[e].x, old.x);
            out[e].y = fmaxf(out[e].y, old.y);
        }
        yout[idx] = out[e];
    }
}

// ---------------- output assembly ----------------------------------------
__global__ void k_zero_agg() {
    int i = blockIdx.x * blockDim.x + threadIdx.x;
    if (i < N_NODES * E_DIM) g_agg[i] = 0u;
}

__global__ void k_zero_out(float4* __restrict__ p, long long n4) {
    long long i = (long long)blockIdx.x * blockDim.x + threadIdx.x;
    long long stride = (long long)gridDim.x * blockDim.x;
    float4 z = make_float4(0.f, 0.f, 0.f, 0.f);
    for (; i < n4; i += stride) p[i] = z;
}

__global__ void k_init_winner() {
    int i = blockIdx.x * blockDim.x + threadIdx.x;
    if (i < N_NODES * N_NODES) g_winner[i] = -1;
}

__global__ void k_winner(const int* __restrict__ ei) {
    int e = blockIdx.x * blockDim.x + threadIdx.x;
    if (e >= N_EDGES) return;
    int key = ei[e] * N_NODES + ei[N_EDGES + e];
    atomicMax(&g_winner[key], e);   // last (largest index) edge wins
}

__global__ void k_scatter(float* __restrict__ out, const int* __restrict__ ei) {
    int tid = threadIdx.x, w = tid >> 5, l = tid & 31;
    int e = blockIdx.x * WPB + w;
    if (e >= N_EDGES) return;
    int key = ei[e] * N_NODES + ei[N_EDGES + e];
    if (g_winner[key] == e) {
        ((float2*)out)[(size_t)key * 32 + l] = ((const float2*)g_y)[(size_t)e * 32 + l];
    }
}

__global__ void k_copyx(float* __restrict__ out) {
    int i = blockIdx.x * blockDim.x + threadIdx.x;
    if (i < N_NODES * E_DIM)
        out[(size_t)N_NODES * N_NODES * E_DIM + i] = g_x[i];
}

// ---------------- launch ---------------------------------------------------
extern "C" void kernel_launch(void* const* d_in, const int* in_sizes, int n_in,
                              void* d_out, int out_size) {
    const float* v      = (const float*)d_in[0];
    const float* labels = (const float*)d_in[1];
    const int*   ei     = (const int*)  d_in[4];
    const float* hxW1 = (const float*)d_in[6];
    const float* hxb1 = (const float*)d_in[7];
    const float* hxW2 = (const float*)d_in[8];
    const float* hxb2 = (const float*)d_in[9];
    const float* hyW1 = (const float*)d_in[10];
    const float* hyb1 = (const float*)d_in[11];
    const float* hyW2 = (const float*)d_in[12];
    const float* hyb2 = (const float*)d_in[13];
    const float* fxW1 = (const float*)d_in[14];
    const float* fxb1 = (const float*)d_in[15];
    const float* fxW2 = (const float*)d_in[16];
    const float* fxb2 = (const float*)d_in[17];
    const float* fyW1 = (const float*)d_in[18];
    const float* fyb1 = (const float*)d_in[19];
    const float* fyW2 = (const float*)d_in[20];
    const float* fyb2 = (const float*)d_in[21];
    float* out = (float*)d_out;

    const int NB_EDGE = (N_EDGES + WPB * EB - 1) / (WPB * EB);   // 750
    const int NB_NODE = (N_NODES + WPB - 1) / WPB;               // 188

    // big zero-fill of the dense edge_feat output goes first
    k_zero_out<<<16384, 256>>>((float4*)out, (long long)N_NODES * N_NODES * E_DIM / 4);

    k_prep0<<<(N_NODES + 255) / 256, 256>>>(v, labels);
    k_combine<<<16, 256>>>(fxW1, fyW1, hyW1);
    k_prep_pv<<<(N_NODES * E_DIM + 255) / 256, 256>>>();
    k_hx<<<NB_NODE, 256>>>(hxW1, hxb1, hxW2, hxb2);
    k_zero_agg<<<(N_NODES * E_DIM + 255) / 256, 256>>>();
    k_xupdate<<<NB_NODE, 256>>>(1);                              // init: projections only
    k_edge_simple<<<NB_EDGE, 256>>>(ei, hyb1, hyW2, hyb2, 0);    // y init (hy)

    for (int t = 0; t < N_LOOP; t++) {
        k_edge_fx<<<NB_EDGE, 256>>>(ei, fxb1, fxW2, fxb2);
        k_xupdate<<<NB_NODE, 256>>>(0);
        k_edge_simple<<<NB_EDGE, 256>>>(ei, fyb1, fyW2, fyb2, 1); // y = max(y, fy)
    }

    k_init_winner<<<(N_NODES * N_NODES + 255) / 256, 256>>>();
    k_winner<<<(N_EDGES + 255) / 256, 256>>>(ei);
    k_scatter<<<(N_EDGES + WPB - 1) / WPB, 256>>>(out, ei);
    k_copyx<<<(N_NODES * E_DIM + 255) / 256, 256>>>(out);
}

// round 7
// speedup vs baseline: 1.0312x; 1.0312x over previous
#include <cuda_runtime.h>
#include <cstddef>

#define N_NODES 1500
#define D_VC    8
#define E_DIM   64
#define N_EDGES 24000
#define N_LOOP  10
#define WPB     8     // warps per block
#define EB      4     // edges per warp

// ---------------- device scratch (static, allocation-free) ----------------
__device__ __align__(16) float    g_vc [N_NODES * D_VC];
__device__ __align__(16) float    g_goal[D_VC];
__device__ __align__(16) float    g_x  [N_NODES * E_DIM];
__device__ __align__(16) float    g_y  [N_EDGES * E_DIM];
__device__ __align__(16) float    g_PA [N_NODES * E_DIM];   // x @ A_fx  (src in fx)
__device__ __align__(16) float    g_PB [N_NODES * E_DIM];   // x @ B_fx  (tgt in fx)
__device__ __align__(16) float    g_RA [N_NODES * E_DIM];   // x @ A_fy  (tgt in fy)
__device__ __align__(16) float    g_RB [N_NODES * E_DIM];   // x @ B_fy  (src in fy)
__device__ __align__(16) float    g_Pv [N_NODES * E_DIM];   // vc @ A_hy (tgt)
__device__ __align__(16) float    g_Qv [N_NODES * E_DIM];   // vc @ B_hy (src)
__device__ __align__(16) unsigned g_agg[N_NODES * E_DIM];
__device__ __align__(16) float    g_Afx[E_DIM * E_DIM];
__device__ __align__(16) float    g_Bfx[E_DIM * E_DIM];
__device__ __align__(16) float    g_Cfx[E_DIM * E_DIM];
__device__ __align__(16) float    g_Afy[E_DIM * E_DIM];
__device__ __align__(16) float    g_Bfy[E_DIM * E_DIM];
__device__ __align__(16) float    g_Ahy[D_VC * E_DIM];
__device__ __align__(16) float    g_Bhy[D_VC * E_DIM];
__device__ int g_winner[N_NODES * N_NODES];

// ---------------- order-preserving float<->u32 encoding for atomicMax ------
__device__ __forceinline__ unsigned encf(float f) {
    unsigned u = __float_as_uint(f);
    return (u & 0x80000000u) ? ~u : (u | 0x80000000u);
}
__device__ __forceinline__ float decf(unsigned e) {
    return __uint_as_float((e & 0x80000000u) ? (e & 0x7FFFFFFFu) : ~e);
}

// ---------------- prep kernels --------------------------------------------
__global__ void k_prep0(const float* __restrict__ v, const float* __restrict__ labels) {
    int n = blockIdx.x * blockDim.x + threadIdx.x;
    if (n >= N_NODES) return;
    float row[D_VC];
#pragma unroll
    for (int c = 0; c < 7; c++) row[c] = v[n * 7 + c];
    row[7] = labels[n];
#pragma unroll
    for (int c = 0; c < 8; c++) g_vc[n * 8 + c] = row[c];
    if (row[7] > 0.5f) {
#pragma unroll
        for (int c = 0; c < 8; c++) g_goal[c] = row[c];
    }
}

__global__ void k_combine(const float* __restrict__ fxW1,
                          const float* __restrict__ fyW1,
                          const float* __restrict__ hyW1) {
    int i = blockIdx.x * blockDim.x + threadIdx.x;
    if (i < 4096) {
        float a = fxW1[i];
        g_Afx[i] = a + fxW1[4096 + i];
        g_Bfx[i] = fxW1[8192 + i] - a;
        g_Cfx[i] = fxW1[12288 + i];
        float b = fyW1[i];
        g_Afy[i] = b + fyW1[4096 + i];
        g_Bfy[i] = fyW1[8192 + i] - b;
    }
    if (i < 512) {
        float c = hyW1[i];
        g_Ahy[i] = c + hyW1[512 + i];
        g_Bhy[i] = hyW1[1024 + i] - c;
    }
}

__global__ void k_prep_pv() {
    int i = blockIdx.x * blockDim.x + threadIdx.x;
    if (i >= N_NODES * E_DIM) return;
    int n = i >> 6, j = i & 63;
    float s = 0.f, q = 0.f;
#pragma unroll
    for (int k = 0; k < 8; k++) {
        float vk = g_vc[n * 8 + k];
        s += vk * g_Ahy[k * 64 + j];
        q += vk * g_Bhy[k * 64 + j];
    }
    g_Pv[i] = s;
    g_Qv[i] = q;
}

// ---------------- hx: x init MLP (per node) -------------------------------
__global__ void k_hx(const float* __restrict__ W1, const float* __restrict__ b1,
                     const float* __restrict__ W2, const float* __restrict__ b2) {
    __shared__ __align__(16) float sW1[32 * 64];
    __shared__ __align__(16) float sW2[64 * 64];
    __shared__ float sB1[64], sB2[64];
    __shared__ __align__(16) float sIn[WPB][32];
    __shared__ __align__(16) float sH[WPB][64];
    int tid = threadIdx.x;
    for (int i = tid; i < 2048; i += 256) sW1[i] = W1[i];
    for (int i = tid; i < 4096; i += 256) sW2[i] = W2[i];
    if (tid < 64) { sB1[tid] = b1[tid]; sB2[tid] = b2[tid]; }
    __syncthreads();
    int w = tid >> 5, l = tid & 31;
    int n = blockIdx.x * WPB + w;
    if (n >= N_NODES) return;
    {
        int g = l >> 3, r = l & 7;
        float vcv = g_vc[n * 8 + r];
        float gv  = g_goal[r];
        float dd  = vcv - gv;
        float val = (g == 0) ? vcv : (g == 1) ? gv : (g == 2) ? dd : dd * dd;
        sIn[w][l] = val;
    }
    __syncwarp();
    const float2* sW1_2 = (const float2*)sW1;
    float2 acc = ((const float2*)sB1)[l];
#pragma unroll 8
    for (int k = 0; k < 32; k++) {
        float vk  = sIn[w][k];
        float2 wv = sW1_2[k * 32 + l];
        acc.x += vk * wv.x; acc.y += vk * wv.y;
    }
    acc.x = fmaxf(acc.x, 0.f); acc.y = fmaxf(acc.y, 0.f);
    ((float2*)sH[w])[l] = acc;
    __syncwarp();
    const float2* sW2_2 = (const float2*)sW2;
    float2 o = ((const float2*)sB2)[l];
#pragma unroll 8
    for (int k = 0; k < 64; k++) {
        float hk  = sH[w][k];
        float2 wv = sW2_2[k * 32 + l];
        o.x += hk * wv.x; o.y += hk * wv.y;
    }
    ((float2*)g_x)[n * 32 + l] = o;
}

// ---------------- x update (+agg reset) + all 4 node projections ----------
__global__ void k_xupdate(int initmode) {
    __shared__ __align__(16) float xs[WPB][64];
    int tid = threadIdx.x, w = tid >> 5, l = tid & 31;
    int n = blockIdx.x * WPB + w;
    if (n >= N_NODES) return;
    float2* x2 = (float2*)g_x;
    float2 xv = x2[n * 32 + l];
    if (!initmode) {
        int base = n * 64 + 2 * l;
        unsigned a0 = g_agg[base], a1 = g_agg[base + 1];
        g_agg[base] = 0u; g_agg[base + 1] = 0u;
        float f0 = a0 ? decf(a0) : 0.f;
        float f1 = a1 ? decf(a1) : 0.f;
        xv.x = fmaxf(xv.x, f0); xv.y = fmaxf(xv.y, f1);
        x2[n * 32 + l] = xv;
    }
    ((float2*)xs[w])[l] = xv;
    __syncwarp();
    const float2* WA = (const float2*)g_Afx;
    const float2* WB = (const float2*)g_Bfx;
    const float2* WC = (const float2*)g_Afy;
    const float2* WD = (const float2*)g_Bfy;
    float2 aA = make_float2(0.f, 0.f), aB = aA, aC = aA, aD = aA;
#pragma unroll 4
    for (int k = 0; k < 64; k++) {
        float xk = xs[w][k];
        float2 wa = __ldg(WA + k * 32 + l);
        float2 wb = __ldg(WB + k * 32 + l);
        float2 wc = __ldg(WC + k * 32 + l);
        float2 wd = __ldg(WD + k * 32 + l);
        aA.x += xk * wa.x; aA.y += xk * wa.y;
        aB.x += xk * wb.x; aB.y += xk * wb.y;
        aC.x += xk * wc.x; aC.y += xk * wc.y;
        aD.x += xk * wd.x; aD.y += xk * wd.y;
    }
    ((float2*)g_PA)[n * 32 + l] = aA;
    ((float2*)g_PB)[n * 32 + l] = aB;
    ((float2*)g_RA)[n * 32 + l] = aC;
    ((float2*)g_RB)[n * 32 + l] = aD;
}

// ---------------- fx message kernel (iteration 0 only) --------------------
__global__ void k_edge_fx(const int* __restrict__ ei,
                          const float* __restrict__ b1,
                          const float* __restrict__ W2,
                          const float* __restrict__ b2) {
    __shared__ __align__(16) float sW1[64 * 64];   // C_fx (y weights)
    __shared__ __align__(16) float sW2[64 * 64];
    __shared__ __align__(16) float sStage[WPB][EB][64];
    __shared__ float sB1[64], sB2[64];
    int tid = threadIdx.x;
    for (int i = tid; i < 4096; i += 256) { sW1[i] = g_Cfx[i]; sW2[i] = W2[i]; }
    if (tid < 64) { sB1[tid] = b1[tid]; sB2[tid] = b2[tid]; }
    __syncthreads();
    int w = tid >> 5, l = tid & 31;
    int ebase = (blockIdx.x * WPB + w) * EB;
    const float2* PA2 = (const float2*)g_PA;
    const float2* PB2 = (const float2*)g_PB;
    const float2* y2  = (const float2*)g_y;
    float2 b1v = ((const float2*)sB1)[l];
    int src[EB], tgt[EB];
    float2 acc[EB];
#pragma unroll
    for (int e = 0; e < EB; e++) {
        int eg = ebase + e;
        bool valid = (eg < N_EDGES);
        int eg0 = valid ? eg : 0;
        src[e] = ei[eg0];
        tgt[e] = ei[N_EDGES + eg0];
        float2 pa = PA2[src[e] * 32 + l];
        float2 pb = PB2[tgt[e] * 32 + l];
        acc[e].x = pa.x + pb.x + b1v.x;
        acc[e].y = pa.y + pb.y + b1v.y;
        ((float2*)sStage[w][e])[l] = y2[(size_t)eg0 * 32 + l];
    }
    __syncwarp();
    const float2* sW1_2 = (const float2*)sW1;
#pragma unroll 8
    for (int k = 0; k < 64; k++) {
        float2 wv = sW1_2[k * 32 + l];
#pragma unroll
        for (int e = 0; e < EB; e++) {
            float yk = sStage[w][e][k];
            acc[e].x += yk * wv.x; acc[e].y += yk * wv.y;
        }
    }
    __syncwarp();
#pragma unroll
    for (int e = 0; e < EB; e++) {
        float2 h;
        h.x = fmaxf(acc[e].x, 0.f); h.y = fmaxf(acc[e].y, 0.f);
        ((float2*)sStage[w][e])[l] = h;
    }
    __syncwarp();
    const float2* sW2_2 = (const float2*)sW2;
    float2 b2v = ((const float2*)sB2)[l];
    float2 out[EB];
#pragma unroll
    for (int e = 0; e < EB; e++) out[e] = b2v;
#pragma unroll 8
    for (int k = 0; k < 64; k++) {
        float2 wv = sW2_2[k * 32 + l];
#pragma unroll
        for (int e = 0; e < EB; e++) {
            float hk = sStage[w][e][k];
            out[e].x += hk * wv.x; out[e].y += hk * wv.y;
        }
    }
#pragma unroll
    for (int e = 0; e < EB; e++) {
        int eg = ebase + e;
        if (eg >= N_EDGES) break;
        unsigned* ap = g_agg + tgt[e] * 64 + 2 * l;
        atomicMax(ap,     encf(out[e].x));
        atomicMax(ap + 1, encf(out[e].y));
    }
}

// ---------------- FUSED: fy(t) then fx(t+1) in one pass over edges --------
// Both sit between the same pair of grid syncs: fy writes y_new for this edge,
// fx immediately consumes y_new for the SAME edge -> warp-local, no sync.
// Dynamic smem layout: [0:4096) W2_fy | [4096:8192) C_fx | [8192:12288) W2_fx
__global__ void k_fused(const int* __restrict__ ei,
                        const float* __restrict__ fyb1, const float* __restrict__ fyW2,
                        const float* __restrict__ fyb2,
                        const float* __restrict__ fxb1, const float* __restrict__ fxW2,
                        const float* __restrict__ fxb2) {
    extern __shared__ __align__(16) float dsm[];
    float* sW2y = dsm;
    float* sCfx = dsm + 4096;
    float* sW2x = dsm + 8192;
    __shared__ __align__(16) float sStage[WPB][EB][64];
    __shared__ float sB1y[64], sB2y[64], sB1x[64], sB2x[64];
    int tid = threadIdx.x;
    for (int i = tid; i < 4096; i += 256) {
        sW2y[i] = fyW2[i];
        sCfx[i] = g_Cfx[i];
        sW2x[i] = fxW2[i];
    }
    if (tid < 64) {
        sB1y[tid] = fyb1[tid]; sB2y[tid] = fyb2[tid];
        sB1x[tid] = fxb1[tid]; sB2x[tid] = fxb2[tid];
    }
    __syncthreads();
    int w = tid >> 5, l = tid & 31;
    int ebase = (blockIdx.x * WPB + w) * EB;
    const float2* PA2 = (const float2*)g_PA;
    const float2* PB2 = (const float2*)g_PB;
    const float2* RA2 = (const float2*)g_RA;
    const float2* RB2 = (const float2*)g_RB;
    float2* y2 = (float2*)g_y;

    int src[EB], tgt[EB];
    // ---- fy layer 1 (from node projections) ----
    {
        float2 b1v = ((const float2*)sB1y)[l];
#pragma unroll
        for (int e = 0; e < EB; e++) {
            int eg = ebase + e;
            int eg0 = (eg < N_EDGES) ? eg : 0;
            src[e] = ei[eg0];
            tgt[e] = ei[N_EDGES + eg0];
            float2 pt = RA2[tgt[e] * 32 + l];
            float2 ps = RB2[src[e] * 32 + l];
            float2 h;
            h.x = fmaxf(pt.x + ps.x + b1v.x, 0.f);
            h.y = fmaxf(pt.y + ps.y + b1v.y, 0.f);
            ((float2*)sStage[w][e])[l] = h;
        }
    }
    __syncwarp();
    // ---- fy layer 2 ----
    float2 yv[EB];
    {
        float2 b2v = ((const float2*)sB2y)[l];
        float2 o[EB];
#pragma unroll
        for (int e = 0; e < EB; e++) o[e] = b2v;
        const float2* W = (const float2*)sW2y;
#pragma unroll 8
        for (int k = 0; k < 64; k++) {
            float2 wv = W[k * 32 + l];
#pragma unroll
            for (int e = 0; e < EB; e++) {
                float hk = sStage[w][e][k];
                o[e].x += hk * wv.x; o[e].y += hk * wv.y;
            }
        }
        __syncwarp();
#pragma unroll
        for (int e = 0; e < EB; e++) {
            int eg = ebase + e;
            int eg0 = (eg < N_EDGES) ? eg : 0;
            size_t idx = (size_t)eg0 * 32 + l;
            float2 old = y2[idx];
            yv[e].x = fmaxf(o[e].x, old.x);
            yv[e].y = fmaxf(o[e].y, old.y);
            if (eg < N_EDGES) y2[idx] = yv[e];
            ((float2*)sStage[w][e])[l] = yv[e];   // stage y_new for fx layer 1
        }
    }
    __syncwarp();
    // ---- fx layer 1: PA[src] + PB[tgt] + y_new @ C ----
    float2 acc[EB];
    {
        float2 b1v = ((const float2*)sB1x)[l];
#pragma unroll
        for (int e = 0; e < EB; e++) {
            float2 pa = PA2[src[e] * 32 + l];
            float2 pb = PB2[tgt[e] * 32 + l];
            acc[e].x = pa.x + pb.x + b1v.x;
            acc[e].y = pa.y + pb.y + b1v.y;
        }
        const float2* W = (const float2*)sCfx;
#pragma unroll 8
        for (int k = 0; k < 64; k++) {
            float2 wv = W[k * 32 + l];
#pragma unroll
            for (int e = 0; e < EB; e++) {
                float yk = sStage[w][e][k];
                acc[e].x += yk * wv.x; acc[e].y += yk * wv.y;
            }
        }
    }
    __syncwarp();
#pragma unroll
    for (int e = 0; e < EB; e++) {
        float2 h;
        h.x = fmaxf(acc[e].x, 0.f); h.y = fmaxf(acc[e].y, 0.f);
        ((float2*)sStage[w][e])[l] = h;
    }
    __syncwarp();
    // ---- fx layer 2 + atomic scatter ----
    {
        float2 b2v = ((const float2*)sB2x)[l];
        float2 o[EB];
#pragma unroll
        for (int e = 0; e < EB; e++) o[e] = b2v;
        const float2* W = (const float2*)sW2x;
#pragma unroll 8
        for (int k = 0; k < 64; k++) {
            float2 wv = W[k * 32 + l];
#pragma unroll
            for (int e = 0; e < EB; e++) {
                float hk = sStage[w][e][k];
                o[e].x += hk * wv.x; o[e].y += hk * wv.y;
            }
        }
#pragma unroll
        for (int e = 0; e < EB; e++) {
            int eg = ebase + e;
            if (eg >= N_EDGES) break;
            unsigned* ap = g_agg + tgt[e] * 64 + 2 * l;
            atomicMax(ap,     encf(o[e].x));
            atomicMax(ap + 1, encf(o[e].y));
        }
    }
}

// ---------------- generic per-edge 2-layer MLP (hy init / fy final) -------
__global__ void k_edge_simple(const int* __restrict__ ei,
                              const float* __restrict__ b1,
                              const float* __restrict__ W2,
                              const float* __restrict__ b2,
                              int which) {
    __shared__ __align__(16) float sW2[64 * 64];
    __shared__ __align__(16) float sStage[WPB][EB][64];
    __shared__ float sB1[64], sB2[64];
    int tid = threadIdx.x;
    for (int i = tid; i < 4096; i += 256) sW2[i] = W2[i];
    if (tid < 64) { sB1[tid] = b1[tid]; sB2[tid] = b2[tid]; }
    __syncthreads();
    int w = tid >> 5, l = tid & 31;
    int ebase = (blockIdx.x * WPB + w) * EB;
    const float2* PT2 = (const float2*)(which ? g_RA : g_Pv);
    const float2* PS2 = (const float2*)(which ? g_RB : g_Qv);
    float2 b1v = ((const float2*)sB1)[l];
    int eg0[EB];
    bool valid[EB];
#pragma unroll
    for (int e = 0; e < EB; e++) {
        int eg = ebase + e;
        valid[e] = (eg < N_EDGES);
        eg0[e] = valid[e] ? eg : 0;
        int s = ei[eg0[e]];
        int t = ei[N_EDGES + eg0[e]];
        float2 pt = PT2[t * 32 + l];
        float2 ps = PS2[s * 32 + l];
        float2 h;
        h.x = fmaxf(pt.x + ps.x + b1v.x, 0.f);
        h.y = fmaxf(pt.y + ps.y + b1v.y, 0.f);
        ((float2*)sStage[w][e])[l] = h;
    }
    __syncwarp();
    const float2* sW2_2 = (const float2*)sW2;
    float2 b2v = ((const float2*)sB2)[l];
    float2 out[EB];
#pragma unroll
    for (int e = 0; e < EB; e++) out[e] = b2v;
#pragma unroll 8
    for (int k = 0; k < 64; k++) {
        float2 wv = sW2_2[k * 32 + l];
#pragma unroll
        for (int e = 0; e < EB; e++) {
            float hk = sStage[w][e][k];
            out[e].x += hk * wv.x; out[e].y += hk * wv.y;
        }
    }
    float2* yout = (float2*)g_y;
#pragma unroll
    for (int e = 0; e < EB; e++) {
        if (!valid[e]) break;
        size_t idx = (size_t)eg0[e] * 32 + l;
        if (which) {
            float2 old = yout[idx];
            out[e].x = fmaxf(out[e].x, old.x);
            out[e].y = fmaxf(out[e].y, old.y);
        }
        yout[idx] = out[e];
    }
}

// ---------------- output assembly ----------------------------------------
__global__ void k_zero_agg() {
    int i = blockIdx.x * blockDim.x + threadIdx.x;
    if (i < N_NODES * E_DIM) g_agg[i] = 0u;
}

__global__ void k_zero_out(float4* __restrict__ p, long long n4) {
    long long i = (long long)blockIdx.x * blockDim.x + threadIdx.x;
    long long stride = (long long)gridDim.x * blockDim.x;
    float4 z = make_float4(0.f, 0.f, 0.f, 0.f);
    for (; i < n4; i += stride) p[i] = z;
}

__global__ void k_init_winner() {
    int i = blockIdx.x * blockDim.x + threadIdx.x;
    if (i < N_NODES * N_NODES) g_winner[i] = -1;
}

__global__ void k_winner(const int* __restrict__ ei) {
    int e = blockIdx.x * blockDim.x + threadIdx.x;
    if (e >= N_EDGES) return;
    int key = ei[e] * N_NODES + ei[N_EDGES + e];
    atomicMax(&g_winner[key], e);   // last (largest index) edge wins
}

__global__ void k_scatter(float* __restrict__ out, const int* __restrict__ ei) {
    int tid = threadIdx.x, w = tid >> 5, l = tid & 31;
    int e = blockIdx.x * WPB + w;
    if (e >= N_EDGES) return;
    int key = ei[e] * N_NODES + ei[N_EDGES + e];
    if (g_winner[key] == e) {
        ((float2*)out)[(size_t)key * 32 + l] = ((const float2*)g_y)[(size_t)e * 32 + l];
    }
}

__global__ void k_copyx(float* __restrict__ out) {
    int i = blockIdx.x * blockDim.x + threadIdx.x;
    if (i < N_NODES * E_DIM)
        out[(size_t)N_NODES * N_NODES * E_DIM + i] = g_x[i];
}

// ---------------- launch ---------------------------------------------------
extern "C" void kernel_launch(void* const* d_in, const int* in_sizes, int n_in,
                              void* d_out, int out_size) {
    const float* v      = (const float*)d_in[0];
    const float* labels = (const float*)d_in[1];
    const int*   ei     = (const int*)  d_in[4];
    const float* hxW1 = (const float*)d_in[6];
    const float* hxb1 = (const float*)d_in[7];
    const float* hxW2 = (const float*)d_in[8];
    const float* hxb2 = (const float*)d_in[9];
    const float* hyW1 = (const float*)d_in[10];
    const float* hyb1 = (const float*)d_in[11];
    const float* hyW2 = (const float*)d_in[12];
    const float* hyb2 = (const float*)d_in[13];
    const float* fxW1 = (const float*)d_in[14];
    const float* fxb1 = (const float*)d_in[15];
    const float* fxW2 = (const float*)d_in[16];
    const float* fxb2 = (const float*)d_in[17];
    const float* fyW1 = (const float*)d_in[18];
    const float* fyb1 = (const float*)d_in[19];
    const float* fyW2 = (const float*)d_in[20];
    const float* fyb2 = (const float*)d_in[21];
    float* out = (float*)d_out;

    const int NB_EDGE = (N_EDGES + WPB * EB - 1) / (WPB * EB);   // 750
    const int NB_NODE = (N_NODES + WPB - 1) / WPB;               // 188
    const int FUSED_DSM = 3 * 4096 * (int)sizeof(float);         // 48KB dynamic

    // One-time host-side setup (first call = correctness run, outside capture)
    static cudaStream_t s2 = nullptr;
    static cudaEvent_t ev_fork = nullptr, ev_join = nullptr;
    static bool attr_set = false;
    if (!s2) {
        cudaStreamCreate(&s2);
        cudaEventCreateWithFlags(&ev_fork, cudaEventDisableTiming);
        cudaEventCreateWithFlags(&ev_join, cudaEventDisableTiming);
    }
    if (!attr_set) {
        cudaFuncSetAttribute(k_fused, cudaFuncAttributeMaxDynamicSharedMemorySize, FUSED_DSM);
        attr_set = true;
    }

    // ---- fork: output zeroing + winner computation run concurrently ----
    cudaEventRecord(ev_fork, 0);
    cudaStreamWaitEvent(s2, ev_fork, 0);
    k_zero_out<<<2048, 256, 0, s2>>>((float4*)out, (long long)N_NODES * N_NODES * E_DIM / 4);
    k_init_winner<<<(N_NODES * N_NODES + 255) / 256, 256, 0, s2>>>();
    k_winner<<<(N_EDGES + 255) / 256, 256, 0, s2>>>(ei);
    cudaEventRecord(ev_join, s2);

    // ---- main stream: GNN loop ----
    k_prep0<<<(N_NODES + 255) / 256, 256>>>(v, labels);
    k_combine<<<16, 256>>>(fxW1, fyW1, hyW1);
    k_prep_pv<<<(N_NODES * E_DIM + 255) / 256, 256>>>();
    k_hx<<<NB_NODE, 256>>>(hxW1, hxb1, hxW2, hxb2);
    k_zero_agg<<<(N_NODES * E_DIM + 255) / 256, 256>>>();
    k_xupdate<<<NB_NODE, 256>>>(1);                              // projections of x_0
    k_edge_simple<<<NB_EDGE, 256>>>(ei, hyb1, hyW2, hyb2, 0);    // y_0 (hy)

    // iteration 0: fx only
    k_edge_fx<<<NB_EDGE, 256>>>(ei, fxb1, fxW2, fxb2);
    k_xupdate<<<NB_NODE, 256>>>(0);
    // iterations 1..9: fused fy(t-1)+fx(t)
    for (int t = 1; t < N_LOOP; t++) {
        k_fused<<<NB_EDGE, 256, FUSED_DSM>>>(ei, fyb1, fyW2, fyb2, fxb1, fxW2, fxb2);
        k_xupdate<<<NB_NODE, 256>>>(0);
    }
    // final fy with x_LOOP
    k_edge_simple<<<NB_EDGE, 256>>>(ei, fyb1, fyW2, fyb2, 1);

    // ---- join and emit output ----
    cudaStreamWaitEvent(0, ev_join, 0);
    k_scatter<<<(N_EDGES + WPB - 1) / WPB, 256>>>(out, ei);
    k_copyx<<<(N_NODES * E_DIM + 255) / 256, 256>>>(out);
}

// round 8
// speedup vs baseline: 1.1746x; 1.1391x over previous
#include <cuda_runtime.h>
#include <cstddef>

#define N_NODES 1500
#define D_VC    8
#define E_DIM   64
#define N_EDGES 24000
#define N_LOOP  10
#define WPB     8          // warps per block
#define NBLK    296        // persistent blocks: 2 per SM on 148-SM B300 (fits 152-SM GB300 too)
#define NWARP   (NBLK * WPB)       // 2368 persistent warps
#define EBP     11                 // edges per warp (2368*11 >= 24000)
#define ZSTRIDE (NBLK * 256)       // zero-fill thread stride
#define ZTOT    36000000u          // 1500*1500*64 floats / 4 = float4 count

// ---------------- device scratch (static, allocation-free) ----------------
__device__ __align__(16) float    g_vc [N_NODES * D_VC];
__device__ __align__(16) float    g_goal[D_VC];
__device__ __align__(16) float    g_x  [N_NODES * E_DIM];
__device__ __align__(16) float    g_y  [N_EDGES * E_DIM];
__device__ __align__(16) float    g_PA [N_NODES * E_DIM];   // x @ A_fx  (src in fx)
__device__ __align__(16) float    g_PB [N_NODES * E_DIM];   // x @ B_fx  (tgt in fx)
__device__ __align__(16) float    g_RA [N_NODES * E_DIM];   // x @ A_fy  (tgt in fy)
__device__ __align__(16) float    g_RB [N_NODES * E_DIM];   // x @ B_fy  (src in fy)
__device__ __align__(16) float    g_Pv [N_NODES * E_DIM];   // vc @ A_hy (tgt)
__device__ __align__(16) float    g_Qv [N_NODES * E_DIM];   // vc @ B_hy (src)
__device__ __align__(16) unsigned g_agg[N_NODES * E_DIM];   // zero at rest (reset by exch)
__device__ __align__(16) float    g_Afx[E_DIM * E_DIM];
__device__ __align__(16) float    g_Bfx[E_DIM * E_DIM];
__device__ __align__(16) float    g_Cfx[E_DIM * E_DIM];
__device__ __align__(16) float    g_Afy[E_DIM * E_DIM];
__device__ __align__(16) float    g_Bfy[E_DIM * E_DIM];
__device__ __align__(16) float    g_Ahy[D_VC * E_DIM];
__device__ __align__(16) float    g_Bhy[D_VC * E_DIM];
__device__ int g_winner[N_NODES * N_NODES];
__device__ unsigned g_bar_gen;   // monotonically increasing across barriers/replays
__device__ unsigned g_bar_cnt;   // returns to 0 after every barrier

// ---------------- helpers --------------------------------------------------
__device__ __forceinline__ unsigned encf(float f) {
    unsigned u = __float_as_uint(f);
    return (u & 0x80000000u) ? ~u : (u | 0x80000000u);
}
__device__ __forceinline__ float decf(unsigned e) {
    return __uint_as_float((e & 0x80000000u) ? (e & 0x7FFFFFFFu) : ~e);
}
__device__ __forceinline__ unsigned long long ffma2(unsigned long long a,
                                                    unsigned long long b,
                                                    unsigned long long c) {
    unsigned long long d;
    asm("fma.rn.f32x2 %0, %1, %2, %3;" : "=l"(d) : "l"(a), "l"(b), "l"(c));
    return d;
}
__device__ __forceinline__ unsigned long long packf2(float lo, float hi) {
    unsigned long long d;
    asm("mov.b64 %0, {%1, %2};" : "=l"(d) : "f"(lo), "f"(hi));
    return d;
}
__device__ __forceinline__ float2 unpackf2(unsigned long long v) {
    float2 r;
    asm("mov.b64 {%0, %1}, %2;" : "=f"(r.x), "=f"(r.y) : "l"(v));
    return r;
}
__device__ __forceinline__ unsigned long long dupf(float h) { return packf2(h, h); }

__device__ __forceinline__ void grid_barrier() {
    __threadfence();
    __syncthreads();
    if (threadIdx.x == 0) {
        unsigned gen = *(volatile unsigned*)&g_bar_gen;
        unsigned prev = atomicAdd(&g_bar_cnt, 1u);
        if (prev == NBLK - 1) {
            g_bar_cnt = 0;
            __threadfence();
            atomicAdd(&g_bar_gen, 1u);
        } else {
            while (*(volatile unsigned*)&g_bar_gen == gen) __nanosleep(32);
        }
    }
    __syncthreads();
}

// ---------------- prep kernels --------------------------------------------
__global__ void k_prep0(const float* __restrict__ v, const float* __restrict__ labels) {
    int n = blockIdx.x * blockDim.x + threadIdx.x;
    if (n >= N_NODES) return;
    float row[D_VC];
#pragma unroll
    for (int c = 0; c < 7; c++) row[c] = v[n * 7 + c];
    row[7] = labels[n];
#pragma unroll
    for (int c = 0; c < 8; c++) g_vc[n * 8 + c] = row[c];
    if (row[7] > 0.5f) {
#pragma unroll
        for (int c = 0; c < 8; c++) g_goal[c] = row[c];
    }
}

__global__ void k_combine(const float* __restrict__ fxW1,
                          const float* __restrict__ fyW1,
                          const float* __restrict__ hyW1) {
    int i = blockIdx.x * blockDim.x + threadIdx.x;
    if (i < 4096) {
        float a = fxW1[i];
        g_Afx[i] = a + fxW1[4096 + i];
        g_Bfx[i] = fxW1[8192 + i] - a;
        g_Cfx[i] = fxW1[12288 + i];
        float b = fyW1[i];
        g_Afy[i] = b + fyW1[4096 + i];
        g_Bfy[i] = fyW1[8192 + i] - b;
    }
    if (i < 512) {
        float c = hyW1[i];
        g_Ahy[i] = c + hyW1[512 + i];
        g_Bhy[i] = hyW1[1024 + i] - c;
    }
}

__global__ void k_prep_pv() {
    int i = blockIdx.x * blockDim.x + threadIdx.x;
    if (i >= N_NODES * E_DIM) return;
    int n = i >> 6, j = i & 63;
    float s = 0.f, q = 0.f;
#pragma unroll
    for (int k = 0; k < 8; k++) {
        float vk = g_vc[n * 8 + k];
        s += vk * g_Ahy[k * 64 + j];
        q += vk * g_Bhy[k * 64 + j];
    }
    g_Pv[i] = s;
    g_Qv[i] = q;
}

// ---------------- hx: x init MLP (per node) -------------------------------
__global__ void k_hx(const float* __restrict__ W1, const float* __restrict__ b1,
                     const float* __restrict__ W2, const float* __restrict__ b2) {
    __shared__ __align__(16) float sW1[32 * 64];
    __shared__ __align__(16) float sW2[64 * 64];
    __shared__ float sB1[64], sB2[64];
    __shared__ __align__(16) float sIn[WPB][32];
    __shared__ __align__(16) float sH[WPB][64];
    int tid = threadIdx.x;
    for (int i = tid; i < 2048; i += 256) sW1[i] = W1[i];
    for (int i = tid; i < 4096; i += 256) sW2[i] = W2[i];
    if (tid < 64) { sB1[tid] = b1[tid]; sB2[tid] = b2[tid]; }
    __syncthreads();
    int w = tid >> 5, l = tid & 31;
    int n = blockIdx.x * WPB + w;
    if (n >= N_NODES) return;
    {
        int g = l >> 3, r = l & 7;
        float vcv = g_vc[n * 8 + r];
        float gv  = g_goal[r];
        float dd  = vcv - gv;
        float val = (g == 0) ? vcv : (g == 1) ? gv : (g == 2) ? dd : dd * dd;
        sIn[w][l] = val;
    }
    __syncwarp();
    const float2* sW1_2 = (const float2*)sW1;
    float2 acc = ((const float2*)sB1)[l];
#pragma unroll 8
    for (int k = 0; k < 32; k++) {
        float vk  = sIn[w][k];
        float2 wv = sW1_2[k * 32 + l];
        acc.x += vk * wv.x; acc.y += vk * wv.y;
    }
    acc.x = fmaxf(acc.x, 0.f); acc.y = fmaxf(acc.y, 0.f);
    ((float2*)sH[w])[l] = acc;
    __syncwarp();
    const float2* sW2_2 = (const float2*)sW2;
    float2 o = ((const float2*)sB2)[l];
#pragma unroll 8
    for (int k = 0; k < 64; k++) {
        float hk  = sH[w][k];
        float2 wv = sW2_2[k * 32 + l];
        o.x += hk * wv.x; o.y += hk * wv.y;
    }
    ((float2*)g_x)[n * 32 + l] = o;
}

// ---------------- persistent loop kernel ----------------------------------
// Phases: N0 | E0(hy + fx0) | N1 | E1(fy+fx) | ... | N10 | E10(final fy)
// sS: per-warp staging of duplicated f32 pairs (ull) for FFMA2 matvecs.
// dyn smem: [0:4096) sW2y (hyW2 then fyW2) | [4096:8192) Cfx | [8192:12288) W2x
__global__ __launch_bounds__(256, 2) void k_persist(
    float4* __restrict__ out4,
    const int* __restrict__ ei,
    const float* __restrict__ hyb1, const float* __restrict__ hyW2, const float* __restrict__ hyb2,
    const float* __restrict__ fyb1, const float* __restrict__ fyW2, const float* __restrict__ fyb2,
    const float* __restrict__ fxb1, const float* __restrict__ fxW2, const float* __restrict__ fxb2)
{
    extern __shared__ __align__(16) float dsm[];
    float* sW2y = dsm;
    float* sCfx = dsm + 4096;
    float* sW2x = dsm + 8192;
    __shared__ unsigned long long sS[WPB][EBP][64];
    __shared__ float sB[6][64];   // 0:hyb1 1:hyb2 2:fyb1 3:fyb2 4:fxb1 5:fxb2

    int tid = threadIdx.x;
    for (int i = tid; i < 4096; i += 256) {
        sW2y[i] = hyW2[i];
        sCfx[i] = g_Cfx[i];
        sW2x[i] = fxW2[i];
    }
    if (tid < 64) {
        sB[0][tid] = hyb1[tid]; sB[1][tid] = hyb2[tid];
        sB[2][tid] = fyb1[tid]; sB[3][tid] = fyb2[tid];
        sB[4][tid] = fxb1[tid]; sB[5][tid] = fxb2[tid];
    }
    __syncthreads();

    int w = tid >> 5, l = tid & 31;
    int wgid = blockIdx.x * WPB + w;
    unsigned zi = (unsigned)(blockIdx.x * 256 + tid);   // zero-fill cursor
    const float4 z4 = make_float4(0.f, 0.f, 0.f, 0.f);

    // node ownership
    int n = wgid;
    bool has_node = (n < N_NODES);
    float2 xv = make_float2(0.f, 0.f);

    // edge ownership (fixed for whole kernel)
    int ebase = wgid * EBP;
    int ec = N_EDGES - ebase;
    if (ec > EBP) ec = EBP;
    if (ec < 0) ec = 0;
    int src[EBP], tgt[EBP];
#pragma unroll
    for (int e = 0; e < EBP; e++) {
        int eg = (e < ec) ? (ebase + e) : 0;
        src[e] = __ldg(ei + eg);
        tgt[e] = __ldg(ei + N_EDGES + eg);
    }
    float2 yv[EBP];

    const float2* PA2 = (const float2*)g_PA;
    const float2* PB2 = (const float2*)g_PB;
    const float2* RA2 = (const float2*)g_RA;
    const float2* RB2 = (const float2*)g_RB;
    const float2* Pv2 = (const float2*)g_Pv;
    const float2* Qv2 = (const float2*)g_Qv;

    for (int t = 0; t <= N_LOOP; t++) {
        // ================= node phase =================
        if (t == 1) {
            // swap sW2y from hyW2 to fyW2 (E0 done; barrier below orders vs E1)
            for (int i = tid; i < 4096; i += 256) sW2y[i] = fyW2[i];
        }
        if (has_node) {
            if (t == 0) {
                xv = ((const float2*)g_x)[n * 32 + l];
            } else {
                unsigned a0 = atomicExch(&g_agg[n * 64 + 2 * l], 0u);
                unsigned a1 = atomicExch(&g_agg[n * 64 + 2 * l + 1], 0u);
                float f0 = a0 ? decf(a0) : 0.f;
                float f1 = a1 ? decf(a1) : 0.f;
                xv.x = fmaxf(xv.x, f0); xv.y = fmaxf(xv.y, f1);
            }
            float* xs = (float*)(&sS[w][0][0]);     // reuse staging as x-broadcast
            ((float2*)xs)[l] = xv;
            __syncwarp();
            const float2* WA = (const float2*)g_Afx;
            const float2* WB = (const float2*)g_Bfx;
            const float2* WC = (const float2*)g_Afy;
            const float2* WD = (const float2*)g_Bfy;
            float2 aA = make_float2(0.f, 0.f), aB = aA, aC = aA, aD = aA;
#pragma unroll 4
            for (int k = 0; k < 64; k++) {
                float xk = xs[k];
                float2 wa = __ldg(WA + k * 32 + l);
                float2 wb = __ldg(WB + k * 32 + l);
                float2 wc = __ldg(WC + k * 32 + l);
                float2 wd = __ldg(WD + k * 32 + l);
                aA.x += xk * wa.x; aA.y += xk * wa.y;
                aB.x += xk * wb.x; aB.y += xk * wb.y;
                aC.x += xk * wc.x; aC.y += xk * wc.y;
                aD.x += xk * wd.x; aD.y += xk * wd.y;
            }
            __stcg((float2*)g_PA + n * 32 + l, aA);
            __stcg((float2*)g_PB + n * 32 + l, aB);
            __stcg((float2*)g_RA + n * 32 + l, aC);
            __stcg((float2*)g_RB + n * 32 + l, aD);
            if (t == N_LOOP) ((float2*)g_x)[n * 32 + l] = xv;
            __syncwarp();
        }
        grid_barrier();

        // ================= edge phase =================
        // zero-fill chunk 1
#pragma unroll
        for (int j = 0; j < 8; j++) { if (zi < ZTOT) { out4[zi] = z4; zi += ZSTRIDE; } }

        // ---- layer 1 of hy (t==0) or fy (t>=1): stage relu hidden as dup pairs
        if (ec > 0) {
            float2 b1 = ((const float2*)sB[(t == 0) ? 0 : 2])[l];
            const float2* Tm = (t == 0) ? Pv2 : RA2;
            const float2* Sm = (t == 0) ? Qv2 : RB2;
#pragma unroll
            for (int e = 0; e < EBP; e++) {
                float2 a = __ldcg(Tm + tgt[e] * 32 + l);
                float2 b = __ldcg(Sm + src[e] * 32 + l);
                float h0 = fmaxf(a.x + b.x + b1.x, 0.f);
                float h1 = fmaxf(a.y + b.y + b1.y, 0.f);
                sS[w][e][2 * l]     = dupf(h0);
                sS[w][e][2 * l + 1] = dupf(h1);
            }
        }
        __syncwarp();
#pragma unroll
        for (int j = 0; j < 8; j++) { if (zi < ZTOT) { out4[zi] = z4; zi += ZSTRIDE; } }

        // ---- layer 2 (hy/fy) via FFMA2
        {
            float2 b2v = ((const float2*)sB[(t == 0) ? 1 : 3])[l];
            unsigned long long binit = packf2(b2v.x, b2v.y);
            unsigned long long o[EBP];
#pragma unroll
            for (int e = 0; e < EBP; e++) o[e] = binit;
            const unsigned long long* wrow = (const unsigned long long*)sW2y;
#pragma unroll 4
            for (int k = 0; k < 64; k++) {
                unsigned long long wv = wrow[k * 32 + l];
#pragma unroll
                for (int e = 0; e < EBP; e++) o[e] = ffma2(wv, sS[w][e][k], o[e]);
            }
#pragma unroll
            for (int e = 0; e < EBP; e++) {
                float2 r = unpackf2(o[e]);
                if (t == 0) yv[e] = r;
                else { yv[e].x = fmaxf(yv[e].x, r.x); yv[e].y = fmaxf(yv[e].y, r.y); }
            }
            if (t == N_LOOP) {
#pragma unroll
                for (int e = 0; e < EBP; e++)
                    if (e < ec) ((float2*)g_y)[(size_t)(ebase + e) * 32 + l] = yv[e];
            }
        }
        __syncwarp();
#pragma unroll
        for (int j = 0; j < 8; j++) { if (zi < ZTOT) { out4[zi] = z4; zi += ZSTRIDE; } }

        if (t < N_LOOP) {
            // ---- fx layer 1: acc = PA[src]+PB[tgt]+b1 + y @ Cfx
            unsigned long long acc[EBP];
            {
                float2 b1x = ((const float2*)sB[4])[l];
#pragma unroll
                for (int e = 0; e < EBP; e++) {
                    // stage y dup-pairs
                    sS[w][e][2 * l]     = dupf(yv[e].x);
                    sS[w][e][2 * l + 1] = dupf(yv[e].y);
                }
                __syncwarp();
#pragma unroll
                for (int e = 0; e < EBP; e++) {
                    float2 pa = __ldcg(PA2 + src[e] * 32 + l);
                    float2 pb = __ldcg(PB2 + tgt[e] * 32 + l);
                    acc[e] = packf2(pa.x + pb.x + b1x.x, pa.y + pb.y + b1x.y);
                }
                const unsigned long long* wrow = (const unsigned long long*)sCfx;
#pragma unroll 4
                for (int k = 0; k < 64; k++) {
                    unsigned long long wv = wrow[k * 32 + l];
#pragma unroll
                    for (int e = 0; e < EBP; e++) acc[e] = ffma2(wv, sS[w][e][k], acc[e]);
                }
            }
            __syncwarp();
#pragma unroll
            for (int j = 0; j < 8; j++) { if (zi < ZTOT) { out4[zi] = z4; zi += ZSTRIDE; } }

            // ---- relu + stage hidden
#pragma unroll
            for (int e = 0; e < EBP; e++) {
                float2 h = unpackf2(acc[e]);
                sS[w][e][2 * l]     = dupf(fmaxf(h.x, 0.f));
                sS[w][e][2 * l + 1] = dupf(fmaxf(h.y, 0.f));
            }
            __syncwarp();

            // ---- fx layer 2 + atomic max scatter
            {
                float2 b2x = ((const float2*)sB[5])[l];
                unsigned long long binit = packf2(b2x.x, b2x.y);
                unsigned long long o[EBP];
#pragma unroll
                for (int e = 0; e < EBP; e++) o[e] = binit;
                const unsigned long long* wrow = (const unsigned long long*)sW2x;
#pragma unroll 4
                for (int k = 0; k < 64; k++) {
                    unsigned long long wv = wrow[k * 32 + l];
#pragma unroll
                    for (int e = 0; e < EBP; e++) o[e] = ffma2(wv, sS[w][e][k], o[e]);
                }
#pragma unroll
                for (int j = 0; j < 8; j++) { if (zi < ZTOT) { out4[zi] = z4; zi += ZSTRIDE; } }
#pragma unroll
                for (int e = 0; e < EBP; e++) {
                    if (e < ec) {
                        float2 r = unpackf2(o[e]);
                        unsigned* ap = g_agg + tgt[e] * 64 + 2 * l;
                        atomicMax(ap,     encf(r.x));
                        atomicMax(ap + 1, encf(r.y));
                    }
                }
            }
            __syncwarp();
#pragma unroll
            for (int j = 0; j < 8; j++) { if (zi < ZTOT) { out4[zi] = z4; zi += ZSTRIDE; } }

            grid_barrier();
        }
    }
    // drain any remaining zero-fill (safety; should already be complete)
    while (zi < ZTOT) { out4[zi] = z4; zi += ZSTRIDE; }
}

// ---------------- output assembly ----------------------------------------
__global__ void k_init_winner() {
    int i = blockIdx.x * blockDim.x + threadIdx.x;
    if (i < N_NODES * N_NODES) g_winner[i] = -1;
}

__global__ void k_winner(const int* __restrict__ ei) {
    int e = blockIdx.x * blockDim.x + threadIdx.x;
    if (e >= N_EDGES) return;
    int key = ei[e] * N_NODES + ei[N_EDGES + e];
    atomicMax(&g_winner[key], e);   // last (largest index) edge wins
}

__global__ void k_scatter(float* __restrict__ out, const int* __restrict__ ei) {
    int tid = threadIdx.x, w = tid >> 5, l = tid & 31;
    int e = blockIdx.x * WPB + w;
    if (e >= N_EDGES) return;
    int key = ei[e] * N_NODES + ei[N_EDGES + e];
    if (g_winner[key] == e) {
        ((float2*)out)[(size_t)key * 32 + l] = ((const float2*)g_y)[(size_t)e * 32 + l];
    }
}

__global__ void k_copyx(float* __restrict__ out) {
    int i = blockIdx.x * blockDim.x + threadIdx.x;
    if (i < N_NODES * E_DIM)
        out[(size_t)N_NODES * N_NODES * E_DIM + i] = g_x[i];
}

// ---------------- launch ---------------------------------------------------
extern "C" void kernel_launch(void* const* d_in, const int* in_sizes, int n_in,
                              void* d_out, int out_size) {
    const float* v      = (const float*)d_in[0];
    const float* labels = (const float*)d_in[1];
    const int*   ei     = (const int*)  d_in[4];
    const float* hxW1 = (const float*)d_in[6];
    const float* hxb1 = (const float*)d_in[7];
    const float* hxW2 = (const float*)d_in[8];
    const float* hxb2 = (const float*)d_in[9];
    const float* hyW1 = (const float*)d_in[10];
    const float* hyb1 = (const float*)d_in[11];
    const float* hyW2 = (const float*)d_in[12];
    const float* hyb2 = (const float*)d_in[13];
    const float* fxW1 = (const float*)d_in[14];
    const float* fxb1 = (const float*)d_in[15];
    const float* fxW2 = (const float*)d_in[16];
    const float* fxb2 = (const float*)d_in[17];
    const float* fyW1 = (const float*)d_in[18];
    const float* fyb1 = (const float*)d_in[19];
    const float* fyW2 = (const float*)d_in[20];
    const float* fyb2 = (const float*)d_in[21];
    float* out = (float*)d_out;

    const int NB_NODE = (N_NODES + WPB - 1) / WPB;     // 188
    const int PERSIST_DSM = 3 * 4096 * (int)sizeof(float);  // 48KB dynamic

    static bool attr_set = false;
    if (!attr_set) {
        cudaFuncSetAttribute(k_persist, cudaFuncAttributeMaxDynamicSharedMemorySize, PERSIST_DSM);
        attr_set = true;
    }

    k_prep0<<<(N_NODES + 255) / 256, 256>>>(v, labels);
    k_combine<<<16, 256>>>(fxW1, fyW1, hyW1);
    k_prep_pv<<<(N_NODES * E_DIM + 255) / 256, 256>>>();
    k_hx<<<NB_NODE, 256>>>(hxW1, hxb1, hxW2, hxb2);
    k_init_winner<<<(N_NODES * N_NODES + 255) / 256, 256>>>();
    k_winner<<<(N_EDGES + 255) / 256, 256>>>(ei);

    k_persist<<<NBLK, 256, PERSIST_DSM>>>((float4*)out, ei,
                                          hyb1, hyW2, hyb2,
                                          fyb1, fyW2, fyb2,
                                          fxb1, fxW2, fxb2);

    k_scatter<<<(N_EDGES + WPB - 1) / WPB, 256>>>(out, ei);
    k_copyx<<<(N_NODES * E_DIM + 255) / 256, 256>>>(out);
}

// round 9
// speedup vs baseline: 1.5449x; 1.3152x over previous
#include <cuda_runtime.h>
#include <cstddef>

typedef unsigned long long ull;

#define N_NODES 1500
#define E_DIM   64
#define N_EDGES 24000
#define N_LOOP  10
#define WPB     8
#define NBLK    296                 // 2 blocks/SM guaranteed resident (148/152-SM parts)
#define NTHREAD (NBLK * 256)        // 75776
#define EBP     11                  // edges per warp
#define ZSTRIDE NTHREAD
#define ZTOT    36000000u           // 1500*1500*64 / 4 float4s (edge_feat region)
#define XOFF    ((size_t)N_NODES * N_NODES * E_DIM)

// ---------------- device scratch (static, allocation-free) ----------------
__device__ __align__(16) float    g_vc [N_NODES * 8];
__device__ __align__(16) float    g_goal[8];
__device__ __align__(16) float    g_PA [N_NODES * E_DIM];
__device__ __align__(16) float    g_PB [N_NODES * E_DIM];
__device__ __align__(16) float    g_RA [N_NODES * E_DIM];
__device__ __align__(16) float    g_RB [N_NODES * E_DIM];
__device__ __align__(16) float    g_Pv [N_NODES * E_DIM];
__device__ __align__(16) float    g_Qv [N_NODES * E_DIM];
__device__ __align__(16) unsigned g_agg[N_NODES * E_DIM];   // zero at rest
__device__ __align__(16) float    g_Afx[E_DIM * E_DIM];
__device__ __align__(16) float    g_Bfx[E_DIM * E_DIM];
__device__ __align__(16) float    g_Cfx[E_DIM * E_DIM];
__device__ __align__(16) float    g_Afy[E_DIM * E_DIM];
__device__ __align__(16) float    g_Bfy[E_DIM * E_DIM];
__device__ __align__(16) float    g_Ahy[8 * E_DIM];
__device__ __align__(16) float    g_Bhy[8 * E_DIM];
__device__ int g_winner[N_NODES * N_NODES];
__device__ unsigned g_bar_gen;   // monotonically increasing across barriers/replays
__device__ unsigned g_bar_cnt;

// ---------------- helpers --------------------------------------------------
__device__ __forceinline__ unsigned encf(float f) {
    unsigned u = __float_as_uint(f);
    return (u & 0x80000000u) ? ~u : (u | 0x80000000u);
}
__device__ __forceinline__ float decf(unsigned e) {
    return __uint_as_float((e & 0x80000000u) ? (e & 0x7FFFFFFFu) : ~e);
}
__device__ __forceinline__ ull ffma2(ull a, ull b, ull c) {
    ull d;
    asm("fma.rn.f32x2 %0, %1, %2, %3;" : "=l"(d) : "l"(a), "l"(b), "l"(c));
    return d;
}
__device__ __forceinline__ ull packf2(float lo, float hi) {
    ull d;
    asm("mov.b64 %0, {%1, %2};" : "=l"(d) : "f"(lo), "f"(hi));
    return d;
}
__device__ __forceinline__ float2 unpackf2(ull v) {
    float2 r;
    asm("mov.b64 {%0, %1}, %2;" : "=f"(r.x), "=f"(r.y) : "l"(v));
    return r;
}

__device__ __forceinline__ void grid_barrier() {
    __threadfence();
    __syncthreads();
    if (threadIdx.x == 0) {
        unsigned gen = *(volatile unsigned*)&g_bar_gen;
        unsigned prev = atomicAdd(&g_bar_cnt, 1u);
        if (prev == NBLK - 1) {
            g_bar_cnt = 0;
            __threadfence();
            atomicAdd(&g_bar_gen, 1u);
        } else {
            while (*(volatile unsigned*)&g_bar_gen == gen) __nanosleep(32);
            __threadfence();
        }
    }
    __syncthreads();
}

// Pair-transpose a 64x64 row-major [k][j] matrix into (kp,jp) uint4 tiles:
// dst viewed as ulonglong2[kp*32 + jp] = { (W[2kp][2jp],   W[2kp+1][2jp]),
//                                          (W[2kp][2jp+1], W[2kp+1][2jp+1]) }
__device__ __forceinline__ void stage_pairs(ull* dst, const float* __restrict__ W, int tid) {
    for (int idx = tid; idx < 1024; idx += 256) {
        int kp = idx >> 5, jp = idx & 31;
        const float* r0 = W + (2 * kp) * 64 + 2 * jp;
        const float* r1 = W + (2 * kp + 1) * 64 + 2 * jp;
        float w00 = r0[0], w01 = r0[1];
        float w10 = r1[0], w11 = r1[1];
        dst[2 * idx]     = packf2(w00, w10);
        dst[2 * idx + 1] = packf2(w01, w11);
    }
}

// k-pair matvec over an edge group [E0,EN). Thread handles output cols (2l,2l+1).
// a0/a1 halves hold even-k / odd-k partials; summed at emit.
template <int E0, int EN, typename InitF, typename EmitF>
__device__ __forceinline__ void mv(const ulonglong2* __restrict__ Wp,
                                   const ull (&hrow)[EBP][32], int l,
                                   InitF init, EmitF emit) {
    ull a0[EN - E0], a1[EN - E0];
#pragma unroll
    for (int e = 0; e < EN - E0; e++) {
        float2 b = init(E0 + e);
        a0[e] = packf2(b.x, 0.f);
        a1[e] = packf2(b.y, 0.f);
    }
#pragma unroll 8
    for (int kp = 0; kp < 32; kp++) {
        ulonglong2 wq = Wp[kp * 32 + l];
#pragma unroll
        for (int e = 0; e < EN - E0; e++) {
            ull hv = hrow[E0 + e][kp];
            a0[e] = ffma2(wq.x, hv, a0[e]);
            a1[e] = ffma2(wq.y, hv, a1[e]);
        }
    }
#pragma unroll
    for (int e = 0; e < EN - E0; e++) {
        float2 p = unpackf2(a0[e]), q = unpackf2(a1[e]);
        emit(E0 + e, make_float2(p.x + p.y, q.x + q.y));
    }
}

#define ZBURST()                                                          \
    {                                                                     \
        _Pragma("unroll") for (int j_ = 0; j_ < 8; j_++) {                \
            if (zi < ZTOT) out4[zi] = z4;                                 \
            zi += ZSTRIDE;                                                \
        }                                                                 \
    }

// ---------------- the single mega-kernel ----------------------------------
__global__ __launch_bounds__(256, 2) void k_all(
    float* __restrict__ out,
    const float* __restrict__ v, const float* __restrict__ labels,
    const int* __restrict__ ei,
    const float* __restrict__ hxW1, const float* __restrict__ hxb1,
    const float* __restrict__ hxW2, const float* __restrict__ hxb2,
    const float* __restrict__ hyW1, const float* __restrict__ hyb1,
    const float* __restrict__ hyW2, const float* __restrict__ hyb2,
    const float* __restrict__ fxW1, const float* __restrict__ fxb1,
    const float* __restrict__ fxW2, const float* __restrict__ fxb2,
    const float* __restrict__ fyW1, const float* __restrict__ fyb1,
    const float* __restrict__ fyW2, const float* __restrict__ fyb2)
{
    extern __shared__ __align__(16) ull dsm[];   // 3 * 2048 ull = 48 KB
    ull* W2y = dsm;          // hyW2 then fyW2 (pair-transposed)
    ull* WCx = dsm + 2048;   // Cfx
    ull* W2x = dsm + 4096;   // fxW2
    __shared__ ull   sH[WPB][EBP][32];
    __shared__ float sB[6][64];   // 0:hyb1 1:hyb2 2:fyb1 3:fyb2 4:fxb1 5:fxb2

    int tid = threadIdx.x, w = tid >> 5, l = tid & 31;
    int gt = blockIdx.x * 256 + tid;
    int wgid = blockIdx.x * WPB + w;
    float4* out4 = (float4*)out;
    const float4 z4 = make_float4(0.f, 0.f, 0.f, 0.f);
    unsigned zi = (unsigned)gt;

    // ================= P0: inputs -> scratch =================
    if (gt < N_NODES) {
        float row[8];
#pragma unroll
        for (int c = 0; c < 7; c++) row[c] = v[gt * 7 + c];
        row[7] = labels[gt];
#pragma unroll
        for (int c = 0; c < 8; c++) g_vc[gt * 8 + c] = row[c];
        if (row[7] > 0.5f) {
#pragma unroll
            for (int c = 0; c < 8; c++) g_goal[c] = row[c];
        }
    }
    if (gt < 4096) {
        float a = fxW1[gt];
        g_Afx[gt] = a + fxW1[4096 + gt];
        g_Bfx[gt] = fxW1[8192 + gt] - a;
        g_Cfx[gt] = fxW1[12288 + gt];
        float b = fyW1[gt];
        g_Afy[gt] = b + fyW1[4096 + gt];
        g_Bfy[gt] = fyW1[8192 + gt] - b;
    }
    if (gt < 512) {
        float c = hyW1[gt];
        g_Ahy[gt] = c + hyW1[512 + gt];
        g_Bhy[gt] = hyW1[1024 + gt] - c;
    }
    for (int i = gt; i < N_NODES * N_NODES; i += NTHREAD) g_winner[i] = -1;
    grid_barrier();

    // ================= P1: derived state =================
    if (gt < N_EDGES)
        atomicMax(&g_winner[ei[gt] * N_NODES + ei[N_EDGES + gt]], gt);
    for (int i = gt; i < N_NODES * E_DIM; i += NTHREAD) {
        int nn = i >> 6, j = i & 63;
        float s = 0.f, q = 0.f;
#pragma unroll
        for (int k = 0; k < 8; k++) {
            float vk = g_vc[nn * 8 + k];
            s += vk * g_Ahy[k * 64 + j];
            q += vk * g_Bhy[k * 64 + j];
        }
        __stcg(&g_Pv[i], s);
        __stcg(&g_Qv[i], q);
    }
    stage_pairs(W2y, hyW2, tid);
    stage_pairs(WCx, g_Cfx, tid);
    stage_pairs(W2x, fxW2, tid);
    if (tid < 64) {
        sB[0][tid] = hyb1[tid]; sB[1][tid] = hyb2[tid];
        sB[2][tid] = fyb1[tid]; sB[3][tid] = fyb2[tid];
        sB[4][tid] = fxb1[tid]; sB[5][tid] = fxb2[tid];
    }

    // hx: per node-warp, result kept in registers
    int n = wgid;
    bool has_node = (n < N_NODES);
    float2 xv = make_float2(0.f, 0.f);
    if (has_node) {
        float* xs = (float*)&sH[w][0][0];   // 64 floats scratch
        float* hs = (float*)&sH[w][4][0];
        {
            int g = l >> 3, r = l & 7;
            float vcv = g_vc[n * 8 + r];
            float gv  = g_goal[r];
            float dd  = vcv - gv;
            xs[l] = (g == 0) ? vcv : (g == 1) ? gv : (g == 2) ? dd : dd * dd;
        }
        __syncwarp();
        float2 acc = __ldg((const float2*)hxb1 + l);
#pragma unroll 8
        for (int k = 0; k < 32; k++) {
            float vk  = xs[k];
            float2 wv = __ldg((const float2*)hxW1 + k * 32 + l);
            acc.x += vk * wv.x; acc.y += vk * wv.y;
        }
        acc.x = fmaxf(acc.x, 0.f); acc.y = fmaxf(acc.y, 0.f);
        ((float2*)hs)[l] = acc;
        __syncwarp();
        float2 o = __ldg((const float2*)hxb2 + l);
#pragma unroll 8
        for (int k = 0; k < 64; k++) {
            float hk  = hs[k];
            float2 wv = __ldg((const float2*)hxW2 + k * 32 + l);
            o.x += hk * wv.x; o.y += hk * wv.y;
        }
        xv = o;
        __syncwarp();
    }

    // edge ownership (registers for the whole kernel)
    int ebase = wgid * EBP;
    int ec = N_EDGES - ebase;
    if (ec > EBP) ec = EBP;
    if (ec < 0) ec = 0;
    int src[EBP], tgt[EBP];
#pragma unroll
    for (int e = 0; e < EBP; e++) {
        int eg = (e < ec) ? (ebase + e) : 0;
        src[e] = __ldg(ei + eg);
        tgt[e] = __ldg(ei + N_EDGES + eg);
    }
    float2 yv[EBP];

    const float2* PA2 = (const float2*)g_PA;
    const float2* PB2 = (const float2*)g_PB;
    const float2* RA2 = (const float2*)g_RA;
    const float2* RB2 = (const float2*)g_RB;
    const float2* Pv2 = (const float2*)g_Pv;
    const float2* Qv2 = (const float2*)g_Qv;
    const float2* Afx2 = (const float2*)g_Afx;
    const float2* Bfx2 = (const float2*)g_Bfx;
    const float2* Afy2 = (const float2*)g_Afy;
    const float2* Bfy2 = (const float2*)g_Bfy;

    grid_barrier();

    // ================= main loop =================
    for (int t = 0; t <= N_LOOP; t++) {
        // ---- node phase ----
        if (t == 1) stage_pairs(W2y, fyW2, tid);   // swap hyW2 -> fyW2 (barriers order it)
        if (has_node) {
            if (t > 0) {
                unsigned a0 = atomicExch(&g_agg[n * 64 + 2 * l], 0u);
                unsigned a1 = atomicExch(&g_agg[n * 64 + 2 * l + 1], 0u);
                xv.x = fmaxf(xv.x, a0 ? decf(a0) : 0.f);
                xv.y = fmaxf(xv.y, a1 ? decf(a1) : 0.f);
            }
            float* xs = (float*)&sH[w][0][0];
            ((float2*)xs)[l] = xv;
            __syncwarp();
            float2 aA = make_float2(0.f, 0.f), aB = aA, aC = aA, aD = aA;
#pragma unroll 4
            for (int k = 0; k < 64; k++) {
                float xk = xs[k];
                float2 wa = __ldg(Afx2 + k * 32 + l);
                float2 wb = __ldg(Bfx2 + k * 32 + l);
                float2 wc = __ldg(Afy2 + k * 32 + l);
                float2 wd = __ldg(Bfy2 + k * 32 + l);
                aA.x += xk * wa.x; aA.y += xk * wa.y;
                aB.x += xk * wb.x; aB.y += xk * wb.y;
                aC.x += xk * wc.x; aC.y += xk * wc.y;
                aD.x += xk * wd.x; aD.y += xk * wd.y;
            }
            __stcg((float2*)g_PA + n * 32 + l, aA);
            __stcg((float2*)g_PB + n * 32 + l, aB);
            __stcg((float2*)g_RA + n * 32 + l, aC);
            __stcg((float2*)g_RB + n * 32 + l, aD);
            if (t == N_LOOP)   // emit x into output tail, straight from registers
                *(float2*)(out + XOFF + (size_t)n * 64 + 2 * l) = xv;
            __syncwarp();
        }
        grid_barrier();

        // ---- edge phase ----
        // layer 1 of hy (t==0) / fy: stage relu hidden as (h[2k],h[2k+1]) pairs
        {
            float2 b1 = ((const float2*)sB[(t == 0) ? 0 : 2])[l];
            const float2* Tm = (t == 0) ? Pv2 : RA2;
            const float2* Sm = (t == 0) ? Qv2 : RB2;
#pragma unroll
            for (int e = 0; e < EBP; e++) {
                float2 a = __ldcg(Tm + tgt[e] * 32 + l);
                float2 b = __ldcg(Sm + src[e] * 32 + l);
                sH[w][e][l] = packf2(fmaxf(a.x + b.x + b1.x, 0.f),
                                     fmaxf(a.y + b.y + b1.y, 0.f));
            }
        }
        __syncwarp();
        ZBURST();

        // layer 2 of hy/fy -> yv
        {
            float2 b2 = ((const float2*)sB[(t == 0) ? 1 : 3])[l];
            const ulonglong2* Wp = (const ulonglong2*)W2y;
            auto init = [&](int) { return b2; };
            auto emit = [&](int e, float2 r) {
                if (t == 0) yv[e] = r;
                else { yv[e].x = fmaxf(yv[e].x, r.x); yv[e].y = fmaxf(yv[e].y, r.y); }
            };
            mv<0, 6>(Wp, sH[w], l, init, emit);
            mv<6, EBP>(Wp, sH[w], l, init, emit);
        }
        ZBURST();

        if (t == N_LOOP) {
            // scatter winner rows straight from registers (zero-fill done @ t==9)
#pragma unroll
            for (int e = 0; e < EBP; e++) {
                if (e < ec) {
                    int key = src[e] * N_NODES + tgt[e];
                    if (__ldg(&g_winner[key]) == ebase + e)
                        ((float2*)out)[(size_t)key * 32 + l] = yv[e];
                }
            }
            break;
        }

        // stage y for fx layer 1
        __syncwarp();
#pragma unroll
        for (int e = 0; e < EBP; e++) sH[w][e][l] = packf2(yv[e].x, yv[e].y);
        __syncwarp();
        ZBURST();

        // fx layer 1: PA[src] + PB[tgt] + b1 + y @ Cfx, relu -> restage
        {
            float2 b1x = ((const float2*)sB[4])[l];
            const ulonglong2* Wp = (const ulonglong2*)WCx;
            auto init = [&](int e) {
                float2 pa = __ldcg(PA2 + src[e] * 32 + l);
                float2 pb = __ldcg(PB2 + tgt[e] * 32 + l);
                return make_float2(pa.x + pb.x + b1x.x, pa.y + pb.y + b1x.y);
            };
            auto emit = [&](int e, float2 r) {
                sH[w][e][l] = packf2(fmaxf(r.x, 0.f), fmaxf(r.y, 0.f));
            };
            mv<0, 6>(Wp, sH[w], l, init, emit);
            mv<6, EBP>(Wp, sH[w], l, init, emit);
        }
        __syncwarp();
        ZBURST();

        // fx layer 2 + atomic max scatter into agg
        {
            float2 b2x = ((const float2*)sB[5])[l];
            const ulonglong2* Wp = (const ulonglong2*)W2x;
            auto init = [&](int) { return b2x; };
            auto emit = [&](int e, float2 r) {
                if (e < ec) {
                    unsigned* ap = g_agg + tgt[e] * 64 + 2 * l;
                    atomicMax(ap,     encf(r.x));
                    atomicMax(ap + 1, encf(r.y));
                }
            };
            mv<0, 6>(Wp, sH[w], l, init, emit);
            ZBURST();
            mv<6, EBP>(Wp, sH[w], l, init, emit);
        }
        ZBURST();
        ZBURST();

        if (t == N_LOOP - 1) {   // guarantee edge_feat zero-fill complete before scatter
            while (zi < ZTOT) { out4[zi] = z4; zi += ZSTRIDE; }
        }
        grid_barrier();
    }
}

// ---------------- launch ---------------------------------------------------
extern "C" void kernel_launch(void* const* d_in, const int* in_sizes, int n_in,
                              void* d_out, int out_size) {
    const float* v      = (const float*)d_in[0];
    const float* labels = (const float*)d_in[1];
    const int*   ei     = (const int*)  d_in[4];
    const float* hxW1 = (const float*)d_in[6];
    const float* hxb1 = (const float*)d_in[7];
    const float* hxW2 = (const float*)d_in[8];
    const float* hxb2 = (const float*)d_in[9];
    const float* hyW1 = (const float*)d_in[10];
    const float* hyb1 = (const float*)d_in[11];
    const float* hyW2 = (const float*)d_in[12];
    const float* hyb2 = (const float*)d_in[13];
    const float* fxW1 = (const float*)d_in[14];
    const float* fxb1 = (const float*)d_in[15];
    const float* fxW2 = (const float*)d_in[16];
    const float* fxb2 = (const float*)d_in[17];
    const float* fyW1 = (const float*)d_in[18];
    const float* fyb1 = (const float*)d_in[19];
    const float* fyW2 = (const float*)d_in[20];
    const float* fyb2 = (const float*)d_in[21];
    float* out = (float*)d_out;

    const int DSM = 3 * 2048 * (int)sizeof(ull);   // 48 KB dynamic
    static bool attr_set = false;
    if (!attr_set) {
        cudaFuncSetAttribute(k_all, cudaFuncAttributeMaxDynamicSharedMemorySize, DSM);
        attr_set = true;
    }

    k_all<<<NBLK, 256, DSM>>>(out, v, labels, ei,
                              hxW1, hxb1, hxW2, hxb2,
                              hyW1, hyb1, hyW2, hyb2,
                              fxW1, fxb1, fxW2, fxb2,
                              fyW1, fyb1, fyW2, fyb2);
}